// round 9
// baseline (speedup 1.0000x reference)
#include <cuda_runtime.h>
#include <math.h>

// Problem constants
#define BB   64     // batch
#define NN   100    // nodes
#define LL   32     // feature dim
#define E1   64     // edge hidden / output dim
#define NH   64     // node hidden dim
#define ND   32     // node output dim
#define ALPHAV 0.1f

// Scratch (device globals — no allocation allowed)
__device__ float g_hA[BB*NN*LL];
__device__ float g_hB[BB*NN*LL];
__device__ float g_U [BB*NN*E1];
__device__ float g_V [BB*NN*E1];
__device__ float g_agg[BB*NN*E1];

__device__ __forceinline__ float lrelu(float x) { return fmaxf(x, ALPHAV * x); }
__device__ __forceinline__ unsigned f2tf32(float x) {
    unsigned u;
    asm("cvt.rna.tf32.f32 %0, %1;" : "=r"(u) : "f"(x));
    return u;
}

// ---------------------------------------------------------------------------
// h = (x @ lin_w + lin_b).reshape(B, N, L)   -> g_hA
// ---------------------------------------------------------------------------
__global__ void lin_kernel(const float* __restrict__ x,
                           const float* __restrict__ w,
                           const float* __restrict__ b)
{
    int idx = blockIdx.x * blockDim.x + threadIdx.x;   // < B*3200
    int bb  = idx / (NN * LL);
    int o   = idx % (NN * LL);
    float acc = b[o];
    #pragma unroll
    for (int k = 0; k < LL; k++)
        acc = fmaf(x[bb * LL + k], w[k * (NN * LL) + o], acc);
    g_hA[idx] = acc;
}

// ---------------------------------------------------------------------------
// Per-node edge-layer0 partials (step 0 only; later steps fused into node).
// ---------------------------------------------------------------------------
__global__ __launch_bounds__(256)
void uv_kernel(const float* __restrict__ h,
               const float* __restrict__ w0,
               const float* __restrict__ b0)
{
    __shared__ float w0s[64 * 64];     // rows 0..63 of ew0 (16KB)
    __shared__ float hs[16][33];
    int tid = threadIdx.x;
    int n0 = blockIdx.x * 16;

    for (int p = tid; p < 64 * 64; p += 256) w0s[p] = w0[p];
    for (int p = tid; p < 16 * LL; p += 256) {
        int nl = p >> 5, m = p & 31;
        hs[nl][m] = h[(n0 + nl) * LL + m];
    }
    __syncthreads();

    int c     = tid & 63;
    int half  = (tid >> 6) & 1;       // 0 -> U, 1 -> V
    int nh    = tid >> 7;             // node-group 0/1
    const float* wp = w0s + half * (LL * 64);
    float bias = half ? 0.0f : b0[c];

    float acc[8];
    #pragma unroll
    for (int s = 0; s < 8; s++) acc[s] = bias;
    #pragma unroll
    for (int m = 0; m < LL; m++) {
        float wv = wp[m * 64 + c];
        #pragma unroll
        for (int s = 0; s < 8; s++)
            acc[s] = fmaf(hs[nh * 8 + s][m], wv, acc[s]);
    }
    float* dst = half ? g_V : g_U;
    #pragma unroll
    for (int s = 0; s < 8; s++)
        dst[(n0 + nh * 8 + s) * E1 + c] = acc[s];
}

// ---------------------------------------------------------------------------
// Edge kernel — tensor-core layer-1 (tf32 mma.sync m16n8k8).
// Dynamic smem layout (floats):
//   Vs    [0, 6400)       : V slab for this batch, 100x64
//   w1f   [6400, 10496)   : W1 in fragment order (tf32)
//   pool  [10496, 14848)  : hjs[100][33] (dist phase) / act0 4x16x68 (mainloop)
//   dists [14848, 15296)  : 4 x 112
// Total 61184 bytes.
// ---------------------------------------------------------------------------
#define EDGE_SMEM_BYTES 61184

__global__ __launch_bounds__(128)
void edge_kernel(const float* __restrict__ h,
                 const float* __restrict__ ew0,   // (65,64): row 64 = dist weights
                 const float* __restrict__ ew1,   // (64,64)
                 const float* __restrict__ eb1)   // (64)
{
    extern __shared__ __align__(16) float dyn[];
    float* Vs    = dyn;
    float* w1f   = dyn + 6400;
    float* pool  = dyn + 10496;
    float* dstsS = dyn + 14848;

    const int bb   = blockIdx.y;
    const int i0   = blockIdx.x * 4;
    const int tid  = threadIdx.x;
    const int w    = tid >> 5;
    const int lane = tid & 31;
    const int i    = i0 + w;
    const int q    = lane & 3;        // quad index (col group)
    const int r    = lane >> 2;       // row index 0..7

    // ---- stage hjs (union with act0 pool) ----
    float (*hjs)[33] = reinterpret_cast<float(*)[33]>(pool);
    for (int idx = tid; idx < NN * LL; idx += 128) {
        int j = idx >> 5, m = idx & 31;
        hjs[j][m] = h[(bb * NN + j) * LL + m];
    }
    // ---- stage V slab for this batch (shared by all 4 warps) ----
    {
        const float4* src = reinterpret_cast<const float4*>(g_V + bb * NN * E1);
        float4* dst = reinterpret_cast<float4*>(Vs);
        for (int p = tid; p < (NN * E1) / 4; p += 128) dst[p] = src[p];
    }
    // ---- repack W1 into fragment order (tf32-rounded) ----
    for (int p = tid; p < 2048; p += 128) {
        int frag = p >> 5, fl = p & 31;
        int kt = frag >> 3, nt = frag & 7, fq = fl & 3, cl = fl >> 2;
        float v0 = ew1[(kt * 8 + fq    ) * 64 + nt * 8 + cl];
        float v1 = ew1[(kt * 8 + fq + 4) * 64 + nt * 8 + cl];
        w1f[2 * p    ] = __uint_as_float(f2tf32(v0));
        w1f[2 * p + 1] = __uint_as_float(f2tf32(v1));
    }
    __syncthreads();

    // ---- distances for this warp's i ----
    for (int j = lane; j < NN; j += 32) {
        float s = 0.0f;
        #pragma unroll
        for (int m = 0; m < LL; m++) {
            float d = hjs[j][m] - hjs[i][m];
            s = fmaf(d, d, s);
        }
        dstsS[w * 112 + j] = sqrtf(s + 1e-12f);
    }
    __syncthreads();   // everyone done reading hjs before act0 overwrites pool

    // ---- per-thread constants ----
    const int kk = 4 * (lane & 15);   // k base this thread fills in act0
    const int tb = lane >> 4;         // 0/1 (which j of the pair per m-step)
    float4 U4  = *reinterpret_cast<const float4*>(&g_U[(bb * NN + i) * E1 + kk]);
    float4 wd4 = *reinterpret_cast<const float4*>(&ew0[64 * E1 + kk]);
    float b1a[8], b1b[8];
    #pragma unroll
    for (int nt = 0; nt < 8; nt++) {
        b1a[nt] = eb1[nt * 8 + 2 * q];
        b1b[nt] = eb1[nt * 8 + 2 * q + 1];
    }

    float* as = pool + w * (16 * 68);
    float sa[8][2];
    #pragma unroll
    for (int nt = 0; nt < 8; nt++) { sa[nt][0] = 0.0f; sa[nt][1] = 0.0f; }

    #pragma unroll 1
    for (int jb = 0; jb < 112; jb += 16) {
        // -- act0 for rows jb..jb+15 (fp32 math, tf32-rounded), V from smem --
        #pragma unroll
        for (int m = 0; m < 8; m++) {
            int jl = 2 * m + tb;
            int jg = jb + jl; if (jg > NN - 1) jg = NN - 1;   // clamp pad rows
            float dj = dstsS[w * 112 + jg];
            float4 v = *reinterpret_cast<const float4*>(&Vs[jg * E1 + kk]);
            float a0 = fmaf(dj, wd4.x, U4.x + v.x); a0 = fmaxf(a0, ALPHAV * a0);
            float a1 = fmaf(dj, wd4.y, U4.y + v.y); a1 = fmaxf(a1, ALPHAV * a1);
            float a2 = fmaf(dj, wd4.z, U4.z + v.z); a2 = fmaxf(a2, ALPHAV * a2);
            float a3 = fmaf(dj, wd4.w, U4.w + v.w); a3 = fmaxf(a3, ALPHAV * a3);
            float4 st;
            st.x = __uint_as_float(f2tf32(a0));
            st.y = __uint_as_float(f2tf32(a1));
            st.z = __uint_as_float(f2tf32(a2));
            st.w = __uint_as_float(f2tf32(a3));
            *reinterpret_cast<float4*>(&as[jl * 68 + kk]) = st;
        }
        __syncwarp();

        // -- D init with bias --
        float d[8][4];
        #pragma unroll
        for (int nt = 0; nt < 8; nt++) {
            d[nt][0] = b1a[nt]; d[nt][1] = b1b[nt];
            d[nt][2] = b1a[nt]; d[nt][3] = b1b[nt];
        }
        // -- 8 k-tiles x 8 n-tiles mma --
        #pragma unroll
        for (int kt = 0; kt < 8; kt++) {
            int kb = kt * 8;
            unsigned a0 = __float_as_uint(as[ r      * 68 + kb + q    ]);
            unsigned a1 = __float_as_uint(as[(r + 8) * 68 + kb + q    ]);
            unsigned a2 = __float_as_uint(as[ r      * 68 + kb + q + 4]);
            unsigned a3 = __float_as_uint(as[(r + 8) * 68 + kb + q + 4]);
            #pragma unroll
            for (int nt = 0; nt < 8; nt++) {
                float2 bp = *reinterpret_cast<const float2*>(&w1f[((kt * 8 + nt) * 32 + lane) * 2]);
                unsigned bf0 = __float_as_uint(bp.x);
                unsigned bf1 = __float_as_uint(bp.y);
                asm volatile(
                    "mma.sync.aligned.m16n8k8.row.col.f32.tf32.tf32.f32 "
                    "{%0,%1,%2,%3}, {%4,%5,%6,%7}, {%8,%9}, {%0,%1,%2,%3};"
                    : "+f"(d[nt][0]), "+f"(d[nt][1]), "+f"(d[nt][2]), "+f"(d[nt][3])
                    : "r"(a0), "r"(a1), "r"(a2), "r"(a3), "r"(bf0), "r"(bf1));
            }
        }
        __syncwarp();   // mma A-reads done before next tile's stores

        // -- epilogue: lrelu + masked row accumulation --
        bool v0 = (jb + r)     < NN;
        bool v1 = (jb + r + 8) < NN;
        #pragma unroll
        for (int nt = 0; nt < 8; nt++) {
            float l0 = fmaxf(d[nt][0], ALPHAV * d[nt][0]);
            float l1 = fmaxf(d[nt][1], ALPHAV * d[nt][1]);
            float l2 = fmaxf(d[nt][2], ALPHAV * d[nt][2]);
            float l3 = fmaxf(d[nt][3], ALPHAV * d[nt][3]);
            if (v0) { sa[nt][0] += l0; sa[nt][1] += l1; }
            if (v1) { sa[nt][0] += l2; sa[nt][1] += l3; }
        }
    }

    // ---- reduce over rows, write agg ----
    #pragma unroll
    for (int nt = 0; nt < 8; nt++) {
        #pragma unroll
        for (int e = 0; e < 2; e++) {
            float v = sa[nt][e];
            v += __shfl_xor_sync(0xffffffff, v, 4);
            v += __shfl_xor_sync(0xffffffff, v, 8);
            v += __shfl_xor_sync(0xffffffff, v, 16);
            sa[nt][e] = v;
        }
    }
    if (lane < 4) {
        #pragma unroll
        for (int nt = 0; nt < 8; nt++) {
            float2 st = make_float2(sa[nt][0], sa[nt][1]);
            *reinterpret_cast<float2*>(&g_agg[(bb * NN + i) * E1 + nt * 8 + 2 * q]) = st;
        }
    }
}

// ---------------------------------------------------------------------------
// Fused node MLP (+ next-step U/V OR final out-projection).
// 16 nodes/block, 256 threads. After layer-0, w0s is dead: next-step edge W0
// is staged into it overlapped with layer-1 compute, so the U/V pass is
// pure-LDS (no exposed global latency).
// ---------------------------------------------------------------------------
__global__ __launch_bounds__(256)
void node_fused_kernel(const float* __restrict__ h,
                       const float* __restrict__ w0,
                       const float* __restrict__ b0,
                       const float* __restrict__ w1,
                       const float* __restrict__ b1,
                       const float* __restrict__ ew0n,  // next-step edge W0 (65,64)
                       const float* __restrict__ eb0n,  // next-step edge b0 (64)
                       const float* __restrict__ ow,    // out_w (32,3)
                       const float* __restrict__ ob,    // out_b (3)
                       float* __restrict__ hout,
                       float* __restrict__ outp,
                       int last)
{
    __shared__ float w0s[(LL + E1) * NH];  // 24576 B (reused for ew0n after L0)
    __shared__ float w1s[NH * ND];         //  8192 B
    __shared__ float z[16][LL + E1];       //  6144 B
    __shared__ float t0s[16][NH];          //  4096 B
    __shared__ float t1s[16][ND];          //  2048 B

    const int t = threadIdx.x;
    const int g = t >> 6;        // node group 0..3 (4 nodes each)
    const int c = t & 63;        // channel
    const int n0 = blockIdx.x * 16;

    for (int p = t; p < (LL + E1) * NH; p += 256) w0s[p] = w0[p];
    for (int p = t; p < NH * ND; p += 256)        w1s[p] = w1[p];
    for (int p = t; p < 16 * LL; p += 256) {
        int n = p >> 5, m = p & 31;
        z[n][m] = h[(n0 + n) * LL + m];
    }
    for (int p = t; p < 16 * E1; p += 256) {
        int n = p >> 6, m = p & 63;
        z[n][LL + m] = g_agg[(n0 + n) * E1 + m];
    }
    __syncthreads();

    // ---- layer 0: 4 nodes per thread ----
    {
        float acc[4];
        float bv = b0[c];
        #pragma unroll
        for (int s = 0; s < 4; s++) acc[s] = bv;
        #pragma unroll
        for (int m = 0; m < LL + E1; m++) {
            float wv = w0s[m * NH + c];
            #pragma unroll
            for (int s = 0; s < 4; s++)
                acc[s] = fmaf(z[g * 4 + s][m], wv, acc[s]);
        }
        #pragma unroll
        for (int s = 0; s < 4; s++)
            t0s[g * 4 + s][c] = fmaxf(acc[s], ALPHAV * acc[s]);
    }
    __syncthreads();

    // ---- stage next-step edge W0 into (now-dead) w0s; overlaps with L1 ----
    if (!last) {
        for (int p = t; p < 64 * 64; p += 256) w0s[p] = ew0n[p];
    }

    // ---- layer 1 (ND=32 outputs; half the channel-threads active) ----
    if (c < ND) {
        float acc[4];
        float bv = b1[c];
        #pragma unroll
        for (int s = 0; s < 4; s++) acc[s] = bv;
        #pragma unroll
        for (int k = 0; k < NH; k++) {
            float wv = w1s[k * ND + c];
            #pragma unroll
            for (int s = 0; s < 4; s++)
                acc[s] = fmaf(t0s[g * 4 + s][k], wv, acc[s]);
        }
        #pragma unroll
        for (int s = 0; s < 4; s++) {
            float v = fmaxf(acc[s], ALPHAV * acc[s]);
            t1s[g * 4 + s][c] = v;
            if (!last) hout[(n0 + g * 4 + s) * ND + c] = v;
        }
    }
    __syncthreads();

    if (last) {
        // ---- final projection: out = tanh(t1 @ ow + ob) ----
        if (t < 48) {
            int n = t / 3, o = t % 3;
            float a = ob[o];
            #pragma unroll
            for (int k = 0; k < ND; k++)
                a = fmaf(t1s[n][k], ow[k * 3 + o], a);
            outp[(n0 + n) * 3 + o] = tanhf(a);
        }
    } else {
        // ---- next-step U/V from t1, weights from smem ----
        float u[4], v4[4];
        float be = eb0n[c];
        #pragma unroll
        for (int s = 0; s < 4; s++) { u[s] = be; v4[s] = 0.0f; }
        #pragma unroll
        for (int m = 0; m < LL; m++) {
            float wu = w0s[ m       * E1 + c];
            float wv = w0s[(LL + m) * E1 + c];
            #pragma unroll
            for (int s = 0; s < 4; s++) {
                float zz = t1s[g * 4 + s][m];
                u[s]  = fmaf(zz, wu, u[s]);
                v4[s] = fmaf(zz, wv, v4[s]);
            }
        }
        #pragma unroll
        for (int s = 0; s < 4; s++) {
            g_U[(n0 + g * 4 + s) * E1 + c] = u[s];
            g_V[(n0 + g * 4 + s) * E1 + c] = v4[s];
        }
    }
}

// ---------------------------------------------------------------------------
extern "C" void kernel_launch(void* const* d_in, const int* in_sizes, int n_in,
                              void* d_out, int out_size)
{
    const float* x     = (const float*)d_in[0];
    const float* lin_w = (const float*)d_in[1];
    const float* lin_b = (const float*)d_in[2];
    const float* ew0[2] = { (const float*)d_in[3],  (const float*)d_in[11] };
    const float* eb0[2] = { (const float*)d_in[4],  (const float*)d_in[12] };
    const float* ew1[2] = { (const float*)d_in[5],  (const float*)d_in[13] };
    const float* eb1[2] = { (const float*)d_in[6],  (const float*)d_in[14] };
    const float* nw0[2] = { (const float*)d_in[7],  (const float*)d_in[15] };
    const float* nb0[2] = { (const float*)d_in[8],  (const float*)d_in[16] };
    const float* nw1[2] = { (const float*)d_in[9],  (const float*)d_in[17] };
    const float* nb1[2] = { (const float*)d_in[10], (const float*)d_in[18] };
    const float* out_w = (const float*)d_in[19];
    const float* out_b = (const float*)d_in[20];
    float* out = (float*)d_out;

    float *hA, *hB;
    cudaGetSymbolAddress((void**)&hA, g_hA);
    cudaGetSymbolAddress((void**)&hB, g_hB);

    cudaFuncSetAttribute(edge_kernel,
                         cudaFuncAttributeMaxDynamicSharedMemorySize,
                         EDGE_SMEM_BYTES);

    lin_kernel<<<(BB * NN * LL) / 256, 256>>>(x, lin_w, lin_b);

    // step 0
    uv_kernel<<<(BB * NN) / 16, 256>>>(hA, ew0[0], eb0[0]);
    dim3 eg(NN / 4, BB);
    edge_kernel<<<eg, 128, EDGE_SMEM_BYTES>>>(hA, ew0[0], ew1[0], eb1[0]);
    // node MLP 0 + U/V for step 1 (fused)
    node_fused_kernel<<<(BB * NN) / 16, 256>>>(hA, nw0[0], nb0[0], nw1[0], nb1[0],
                                               ew0[1], eb0[1], out_w, out_b,
                                               hB, out, 0);
    // step 1
    edge_kernel<<<eg, 128, EDGE_SMEM_BYTES>>>(hB, ew0[1], ew1[1], eb1[1]);
    // node MLP 1 + final projection (fused)
    node_fused_kernel<<<(BB * NN) / 16, 256>>>(hB, nw0[1], nb0[1], nw1[1], nb1[1],
                                               ew0[1], eb0[1], out_w, out_b,
                                               hB, out, 1);
}

// round 10
// speedup vs baseline: 1.2812x; 1.2812x over previous
#include <cuda_runtime.h>
#include <math.h>

// Problem constants
#define BB   64     // batch
#define NN   100    // nodes
#define LL   32     // feature dim
#define E1   64     // edge hidden / output dim
#define NH   64     // node hidden dim
#define ND   32     // node output dim
#define ALPHAV 0.1f

// Scratch (device globals — no allocation allowed)
__device__ float g_hA[BB*NN*LL];
__device__ float g_hB[BB*NN*LL];
__device__ float g_U [BB*NN*E1];
__device__ float g_V [BB*NN*E1];
__device__ float g_agg[BB*NN*E1];

__device__ __forceinline__ float lrelu(float x) { return fmaxf(x, ALPHAV * x); }
__device__ __forceinline__ unsigned f2tf32(float x) {
    unsigned u;
    asm("cvt.rna.tf32.f32 %0, %1;" : "=r"(u) : "f"(x));
    return u;
}

// ---------------------------------------------------------------------------
// h = (x @ lin_w + lin_b).reshape(B, N, L)   -> g_hA
// ---------------------------------------------------------------------------
__global__ void lin_kernel(const float* __restrict__ x,
                           const float* __restrict__ w,
                           const float* __restrict__ b)
{
    int idx = blockIdx.x * blockDim.x + threadIdx.x;   // < B*3200
    int bb  = idx / (NN * LL);
    int o   = idx % (NN * LL);
    float acc = b[o];
    #pragma unroll
    for (int k = 0; k < LL; k++)
        acc = fmaf(x[bb * LL + k], w[k * (NN * LL) + o], acc);
    g_hA[idx] = acc;
}

// ---------------------------------------------------------------------------
// Per-node edge-layer0 partials (step 0 only; later steps fused into node).
// ---------------------------------------------------------------------------
__global__ __launch_bounds__(256)
void uv_kernel(const float* __restrict__ h,
               const float* __restrict__ w0,
               const float* __restrict__ b0)
{
    __shared__ float w0s[64 * 64];     // rows 0..63 of ew0 (16KB)
    __shared__ float hs[16][33];
    int tid = threadIdx.x;
    int n0 = blockIdx.x * 16;

    for (int p = tid; p < 64 * 64; p += 256) w0s[p] = w0[p];
    for (int p = tid; p < 16 * LL; p += 256) {
        int nl = p >> 5, m = p & 31;
        hs[nl][m] = h[(n0 + nl) * LL + m];
    }
    __syncthreads();

    int c     = tid & 63;
    int half  = (tid >> 6) & 1;       // 0 -> U, 1 -> V
    int nh    = tid >> 7;             // node-group 0/1
    const float* wp = w0s + half * (LL * 64);
    float bias = half ? 0.0f : b0[c];

    float acc[8];
    #pragma unroll
    for (int s = 0; s < 8; s++) acc[s] = bias;
    #pragma unroll
    for (int m = 0; m < LL; m++) {
        float wv = wp[m * 64 + c];
        #pragma unroll
        for (int s = 0; s < 8; s++)
            acc[s] = fmaf(hs[nh * 8 + s][m], wv, acc[s]);
    }
    float* dst = half ? g_V : g_U;
    #pragma unroll
    for (int s = 0; s < 8; s++)
        dst[(n0 + nh * 8 + s) * E1 + c] = acc[s];
}

// ---------------------------------------------------------------------------
// Edge kernel — tensor-core layer-1 (tf32 mma.sync m16n8k8).
// R8 structure (static smem, V from L2). w1f repacked so each LDS.128 feeds
// TWO mma (nt-pair adjacent per lane).
// ---------------------------------------------------------------------------
__global__ __launch_bounds__(128)
void edge_kernel(const float* __restrict__ h,
                 const float* __restrict__ ew0,   // (65,64): row 64 = dist weights
                 const float* __restrict__ ew1,   // (64,64)
                 const float* __restrict__ eb1)   // (64)
{
    __shared__ __align__(16) float pool[4 * 16 * 68];   // 17408 B
    __shared__ __align__(16) float w1f[4096];           // 16384 B, paired-frag tf32
    __shared__ __align__(16) float dists_s[4][112];

    const int bb   = blockIdx.y;
    const int i0   = blockIdx.x * 4;
    const int tid  = threadIdx.x;
    const int w    = tid >> 5;
    const int lane = tid & 31;
    const int i    = i0 + w;
    const int q    = lane & 3;        // quad index (col group)
    const int r    = lane >> 2;       // row index 0..7

    // ---- stage hjs (union with act0 pool) ----
    float (*hjs)[33] = reinterpret_cast<float(*)[33]>(pool);
    for (int idx = tid; idx < NN * LL; idx += 128) {
        int j = idx >> 5, m = idx & 31;
        hjs[j][m] = h[(bb * NN + j) * LL + m];
    }
    // ---- repack W1: paired fragment order (tf32) ----
    // float4 at ((kt*4+ntp)*32+lane)*4 = {b0(nt0), b1(nt0), b0(nt1), b1(nt1)}
    for (int p4 = tid; p4 < 1024; p4 += 128) {
        int kt  = p4 >> 7;
        int rem = p4 & 127;
        int ntp = rem >> 5;
        int ln  = rem & 31;
        int fq  = ln & 3, cl = ln >> 2;
        int nt0 = 2 * ntp, nt1 = nt0 + 1;
        float v00 = ew1[(kt * 8 + fq    ) * 64 + nt0 * 8 + cl];
        float v01 = ew1[(kt * 8 + fq + 4) * 64 + nt0 * 8 + cl];
        float v10 = ew1[(kt * 8 + fq    ) * 64 + nt1 * 8 + cl];
        float v11 = ew1[(kt * 8 + fq + 4) * 64 + nt1 * 8 + cl];
        float4 st;
        st.x = __uint_as_float(f2tf32(v00));
        st.y = __uint_as_float(f2tf32(v01));
        st.z = __uint_as_float(f2tf32(v10));
        st.w = __uint_as_float(f2tf32(v11));
        *reinterpret_cast<float4*>(&w1f[p4 * 4]) = st;
    }
    __syncthreads();

    // ---- distances for this warp's i ----
    for (int j = lane; j < NN; j += 32) {
        float s = 0.0f;
        #pragma unroll
        for (int m = 0; m < LL; m++) {
            float d = hjs[j][m] - hjs[i][m];
            s = fmaf(d, d, s);
        }
        dists_s[w][j] = sqrtf(s + 1e-12f);
    }
    __syncthreads();   // everyone done reading hjs before act0 overwrites pool

    // ---- per-thread constants ----
    const int kk = 4 * (lane & 15);   // k base this thread fills in act0
    const int tb = lane >> 4;         // 0/1 (which j of the pair per m-step)
    float4 U4  = *reinterpret_cast<const float4*>(&g_U[(bb * NN + i) * E1 + kk]);
    float4 wd4 = *reinterpret_cast<const float4*>(&ew0[64 * E1 + kk]);
    float b1a[8], b1b[8];
    #pragma unroll
    for (int nt = 0; nt < 8; nt++) {
        b1a[nt] = eb1[nt * 8 + 2 * q];
        b1b[nt] = eb1[nt * 8 + 2 * q + 1];
    }

    float* as = pool + w * (16 * 68);
    float sa[8][2];
    #pragma unroll
    for (int nt = 0; nt < 8; nt++) { sa[nt][0] = 0.0f; sa[nt][1] = 0.0f; }

    #pragma unroll 1
    for (int jb = 0; jb < 112; jb += 16) {
        // -- act0 for rows jb..jb+15 (fp32 math, tf32-rounded) --
        #pragma unroll
        for (int m = 0; m < 8; m++) {
            int jl = 2 * m + tb;
            int jg = jb + jl; if (jg > NN - 1) jg = NN - 1;   // clamp pad rows
            float dj = dists_s[w][jg];
            float4 v = *reinterpret_cast<const float4*>(&g_V[(bb * NN + jg) * E1 + kk]);
            float a0 = fmaf(dj, wd4.x, U4.x + v.x); a0 = fmaxf(a0, ALPHAV * a0);
            float a1 = fmaf(dj, wd4.y, U4.y + v.y); a1 = fmaxf(a1, ALPHAV * a1);
            float a2 = fmaf(dj, wd4.z, U4.z + v.z); a2 = fmaxf(a2, ALPHAV * a2);
            float a3 = fmaf(dj, wd4.w, U4.w + v.w); a3 = fmaxf(a3, ALPHAV * a3);
            float4 st;
            st.x = __uint_as_float(f2tf32(a0));
            st.y = __uint_as_float(f2tf32(a1));
            st.z = __uint_as_float(f2tf32(a2));
            st.w = __uint_as_float(f2tf32(a3));
            *reinterpret_cast<float4*>(&as[jl * 68 + kk]) = st;
        }
        __syncwarp();

        // -- D init with bias --
        float d[8][4];
        #pragma unroll
        for (int nt = 0; nt < 8; nt++) {
            d[nt][0] = b1a[nt]; d[nt][1] = b1b[nt];
            d[nt][2] = b1a[nt]; d[nt][3] = b1b[nt];
        }
        // -- 8 k-tiles x 4 nt-pairs mma; one LDS.128 feeds two mma --
        #pragma unroll
        for (int kt = 0; kt < 8; kt++) {
            int kb = kt * 8;
            unsigned a0 = __float_as_uint(as[ r      * 68 + kb + q    ]);
            unsigned a1 = __float_as_uint(as[(r + 8) * 68 + kb + q    ]);
            unsigned a2 = __float_as_uint(as[ r      * 68 + kb + q + 4]);
            unsigned a3 = __float_as_uint(as[(r + 8) * 68 + kb + q + 4]);
            #pragma unroll
            for (int ntp = 0; ntp < 4; ntp++) {
                float4 bp = *reinterpret_cast<const float4*>(
                    &w1f[((kt * 4 + ntp) * 32 + lane) * 4]);
                int nt0 = 2 * ntp, nt1 = nt0 + 1;
                unsigned bf0 = __float_as_uint(bp.x);
                unsigned bf1 = __float_as_uint(bp.y);
                unsigned bf2 = __float_as_uint(bp.z);
                unsigned bf3 = __float_as_uint(bp.w);
                asm volatile(
                    "mma.sync.aligned.m16n8k8.row.col.f32.tf32.tf32.f32 "
                    "{%0,%1,%2,%3}, {%4,%5,%6,%7}, {%8,%9}, {%0,%1,%2,%3};"
                    : "+f"(d[nt0][0]), "+f"(d[nt0][1]), "+f"(d[nt0][2]), "+f"(d[nt0][3])
                    : "r"(a0), "r"(a1), "r"(a2), "r"(a3), "r"(bf0), "r"(bf1));
                asm volatile(
                    "mma.sync.aligned.m16n8k8.row.col.f32.tf32.tf32.f32 "
                    "{%0,%1,%2,%3}, {%4,%5,%6,%7}, {%8,%9}, {%0,%1,%2,%3};"
                    : "+f"(d[nt1][0]), "+f"(d[nt1][1]), "+f"(d[nt1][2]), "+f"(d[nt1][3])
                    : "r"(a0), "r"(a1), "r"(a2), "r"(a3), "r"(bf2), "r"(bf3));
            }
        }
        __syncwarp();   // mma A-reads done before next tile's stores

        // -- epilogue: lrelu + masked row accumulation --
        bool v0 = (jb + r)     < NN;
        bool v1 = (jb + r + 8) < NN;
        #pragma unroll
        for (int nt = 0; nt < 8; nt++) {
            float l0 = fmaxf(d[nt][0], ALPHAV * d[nt][0]);
            float l1 = fmaxf(d[nt][1], ALPHAV * d[nt][1]);
            float l2 = fmaxf(d[nt][2], ALPHAV * d[nt][2]);
            float l3 = fmaxf(d[nt][3], ALPHAV * d[nt][3]);
            if (v0) { sa[nt][0] += l0; sa[nt][1] += l1; }
            if (v1) { sa[nt][0] += l2; sa[nt][1] += l3; }
        }
    }

    // ---- reduce over rows, write agg ----
    #pragma unroll
    for (int nt = 0; nt < 8; nt++) {
        #pragma unroll
        for (int e = 0; e < 2; e++) {
            float v = sa[nt][e];
            v += __shfl_xor_sync(0xffffffff, v, 4);
            v += __shfl_xor_sync(0xffffffff, v, 8);
            v += __shfl_xor_sync(0xffffffff, v, 16);
            sa[nt][e] = v;
        }
    }
    if (lane < 4) {
        #pragma unroll
        for (int nt = 0; nt < 8; nt++) {
            float2 st = make_float2(sa[nt][0], sa[nt][1]);
            *reinterpret_cast<float2*>(&g_agg[(bb * NN + i) * E1 + nt * 8 + 2 * q]) = st;
        }
    }
}

// ---------------------------------------------------------------------------
// Fused node MLP (+ next-step U/V OR final out-projection).
// 16 nodes/block, 512 threads (grid is only 400 blocks -> raise warps/block).
// ew0n staged in the prologue (overlapped), U/V pass is pure-LDS.
// Dynamic smem layout (floats):
//   w0s  [0,6144)  w1s [6144,8192)  ew0s [8192,12288)
//   z    [12288,13824)  t0s [13824,14848)  t1s [14848,15360)
// ---------------------------------------------------------------------------
#define NODE_SMEM_BYTES 61440

__global__ __launch_bounds__(512)
void node_fused_kernel(const float* __restrict__ h,
                       const float* __restrict__ w0,
                       const float* __restrict__ b0,
                       const float* __restrict__ w1,
                       const float* __restrict__ b1,
                       const float* __restrict__ ew0n,  // next-step edge W0 (65,64)
                       const float* __restrict__ eb0n,  // next-step edge b0 (64)
                       const float* __restrict__ ow,    // out_w (32,3)
                       const float* __restrict__ ob,    // out_b (3)
                       float* __restrict__ hout,
                       float* __restrict__ outp,
                       int last)
{
    extern __shared__ float ndyn[];
    float* w0s  = ndyn;           // 96*64
    float* w1s  = ndyn + 6144;    // 64*32
    float* ew0s = ndyn + 8192;    // 64*64
    float* zb   = ndyn + 12288;   // 16*96
    float* t0s  = ndyn + 13824;   // 16*64
    float* t1s  = ndyn + 14848;   // 16*32

    const int t = threadIdx.x;
    const int g = t >> 6;        // node group 0..7 (2 nodes each)
    const int c = t & 63;        // channel
    const int n0 = blockIdx.x * 16;

    for (int p = t; p < (LL + E1) * NH; p += 512) w0s[p] = w0[p];
    for (int p = t; p < NH * ND; p += 512)        w1s[p] = w1[p];
    if (!last)
        for (int p = t; p < 64 * 64; p += 512)    ew0s[p] = ew0n[p];
    for (int p = t; p < 16 * LL; p += 512) {
        int n = p >> 5, m = p & 31;
        zb[n * 96 + m] = h[(n0 + n) * LL + m];
    }
    for (int p = t; p < 16 * E1; p += 512) {
        int n = p >> 6, m = p & 63;
        zb[n * 96 + LL + m] = g_agg[(n0 + n) * E1 + m];
    }
    __syncthreads();

    // ---- layer 0: 2 nodes per thread ----
    {
        float bv = b0[c];
        float a0 = bv, a1 = bv;
        const float* z0 = zb + (g * 2) * 96;
        const float* z1 = zb + (g * 2 + 1) * 96;
        #pragma unroll
        for (int m = 0; m < LL + E1; m++) {
            float wv = w0s[m * NH + c];
            a0 = fmaf(z0[m], wv, a0);
            a1 = fmaf(z1[m], wv, a1);
        }
        t0s[(g * 2) * NH + c]     = fmaxf(a0, ALPHAV * a0);
        t0s[(g * 2 + 1) * NH + c] = fmaxf(a1, ALPHAV * a1);
    }
    __syncthreads();

    // ---- layer 1 (ND=32 outputs; half the channel-threads active) ----
    if (c < ND) {
        float bv = b1[c];
        float a0 = bv, a1 = bv;
        const float* s0 = t0s + (g * 2) * NH;
        const float* s1 = t0s + (g * 2 + 1) * NH;
        #pragma unroll
        for (int k = 0; k < NH; k++) {
            float wv = w1s[k * ND + c];
            a0 = fmaf(s0[k], wv, a0);
            a1 = fmaf(s1[k], wv, a1);
        }
        float v0 = fmaxf(a0, ALPHAV * a0);
        float v1 = fmaxf(a1, ALPHAV * a1);
        t1s[(g * 2) * ND + c]     = v0;
        t1s[(g * 2 + 1) * ND + c] = v1;
        if (!last) {
            hout[(n0 + g * 2) * ND + c]     = v0;
            hout[(n0 + g * 2 + 1) * ND + c] = v1;
        }
    }
    __syncthreads();

    if (last) {
        // ---- final projection: out = tanh(t1 @ ow + ob) ----
        if (t < 48) {
            int n = t / 3, o = t % 3;
            float a = ob[o];
            #pragma unroll
            for (int k = 0; k < ND; k++)
                a = fmaf(t1s[n * ND + k], ow[k * 3 + o], a);
            outp[(n0 + n) * 3 + o] = tanhf(a);
        }
    } else {
        // ---- next-step U/V from t1, weights from smem (staged in prologue) ----
        float be = eb0n[c];
        float u0 = be, u1 = be, v0 = 0.0f, v1 = 0.0f;
        const float* s0 = t1s + (g * 2) * ND;
        const float* s1 = t1s + (g * 2 + 1) * ND;
        #pragma unroll
        for (int m = 0; m < LL; m++) {
            float wu = ew0s[ m       * E1 + c];
            float wv = ew0s[(LL + m) * E1 + c];
            float z0 = s0[m], z1 = s1[m];
            u0 = fmaf(z0, wu, u0);  u1 = fmaf(z1, wu, u1);
            v0 = fmaf(z0, wv, v0);  v1 = fmaf(z1, wv, v1);
        }
        g_U[(n0 + g * 2) * E1 + c]     = u0;
        g_U[(n0 + g * 2 + 1) * E1 + c] = u1;
        g_V[(n0 + g * 2) * E1 + c]     = v0;
        g_V[(n0 + g * 2 + 1) * E1 + c] = v1;
    }
}

// ---------------------------------------------------------------------------
extern "C" void kernel_launch(void* const* d_in, const int* in_sizes, int n_in,
                              void* d_out, int out_size)
{
    const float* x     = (const float*)d_in[0];
    const float* lin_w = (const float*)d_in[1];
    const float* lin_b = (const float*)d_in[2];
    const float* ew0[2] = { (const float*)d_in[3],  (const float*)d_in[11] };
    const float* eb0[2] = { (const float*)d_in[4],  (const float*)d_in[12] };
    const float* ew1[2] = { (const float*)d_in[5],  (const float*)d_in[13] };
    const float* eb1[2] = { (const float*)d_in[6],  (const float*)d_in[14] };
    const float* nw0[2] = { (const float*)d_in[7],  (const float*)d_in[15] };
    const float* nb0[2] = { (const float*)d_in[8],  (const float*)d_in[16] };
    const float* nw1[2] = { (const float*)d_in[9],  (const float*)d_in[17] };
    const float* nb1[2] = { (const float*)d_in[10], (const float*)d_in[18] };
    const float* out_w = (const float*)d_in[19];
    const float* out_b = (const float*)d_in[20];
    float* out = (float*)d_out;

    float *hA, *hB;
    cudaGetSymbolAddress((void**)&hA, g_hA);
    cudaGetSymbolAddress((void**)&hB, g_hB);

    cudaFuncSetAttribute(node_fused_kernel,
                         cudaFuncAttributeMaxDynamicSharedMemorySize,
                         NODE_SMEM_BYTES);

    lin_kernel<<<(BB * NN * LL) / 256, 256>>>(x, lin_w, lin_b);

    // step 0
    uv_kernel<<<(BB * NN) / 16, 256>>>(hA, ew0[0], eb0[0]);
    dim3 eg(NN / 4, BB);
    edge_kernel<<<eg, 128>>>(hA, ew0[0], ew1[0], eb1[0]);
    // node MLP 0 + U/V for step 1 (fused)
    node_fused_kernel<<<(BB * NN) / 16, 512, NODE_SMEM_BYTES>>>(
        hA, nw0[0], nb0[0], nw1[0], nb1[0],
        ew0[1], eb0[1], out_w, out_b, hB, out, 0);
    // step 1
    edge_kernel<<<eg, 128>>>(hB, ew0[1], ew1[1], eb1[1]);
    // node MLP 1 + final projection (fused)
    node_fused_kernel<<<(BB * NN) / 16, 512, NODE_SMEM_BYTES>>>(
        hB, nw0[1], nb0[1], nw1[1], nb1[1],
        ew0[1], eb0[1], out_w, out_b, hB, out, 1);
}